// round 14
// baseline (speedup 1.0000x reference)
#include <cuda_runtime.h>
#include <math.h>

// Problem constants
#define N      512
#define LOGN   9
#define NIMG   96          // 32 batch * 3 channels
#define NJ     257         // stored half-spectrum columns (0..256)

// Scratch (device globals: allocation-free rule)
__device__ float2 g_spec[(size_t)NIMG * NJ * N];  // [img][j 0..256][h]
__device__ float  g_filt[(size_t)3 * NJ * N];     // [c][j][iu_store] (u digit-reversed)
__device__ float2 g_tw[N];                        // W_512^k

#define RSQ2 0.70710678118654752440f

__device__ __forceinline__ float2 f2add(float2 a, float2 b){ return make_float2(a.x+b.x, a.y+b.y); }
__device__ __forceinline__ float2 f2sub(float2 a, float2 b){ return make_float2(a.x-b.x, a.y-b.y); }
__device__ __forceinline__ float2 cmul(float2 a, float2 b){           // a*b
    return make_float2(a.x*b.x - a.y*b.y, a.x*b.y + a.y*b.x);
}
__device__ __forceinline__ float2 cmulc(float2 w, float2 b){          // conj(w)*b
    return make_float2(w.x*b.x + w.y*b.y, w.x*b.y - w.y*b.x);
}

// 8-point DFT, natural-order in/out, in registers.
__device__ __forceinline__ void dft8(float2* r) {
    float2 t0=f2add(r[0],r[4]), t4=f2sub(r[0],r[4]);
    float2 t1=f2add(r[1],r[5]), t5=f2sub(r[1],r[5]);
    float2 t2=f2add(r[2],r[6]), t6=f2sub(r[2],r[6]);
    float2 t3=f2add(r[3],r[7]), t7=f2sub(r[3],r[7]);
    t5 = make_float2(RSQ2*(t5.x+t5.y),  RSQ2*(t5.y-t5.x));
    t6 = make_float2(t6.y, -t6.x);
    t7 = make_float2(RSQ2*(t7.y-t7.x), -RSQ2*(t7.x+t7.y));
    float2 u0=f2add(t0,t2), u2=f2sub(t0,t2);
    float2 u1=f2add(t1,t3), u3=f2sub(t1,t3);
    float2 u4=f2add(t4,t6), u6=f2sub(t4,t6);
    float2 u5=f2add(t5,t7), u7=f2sub(t5,t7);
    u3 = make_float2(u3.y, -u3.x);
    u7 = make_float2(u7.y, -u7.x);
    r[0]=f2add(u0,u1); r[4]=f2sub(u0,u1);
    r[2]=f2add(u2,u3); r[6]=f2sub(u2,u3);
    r[1]=f2add(u4,u5); r[5]=f2sub(u4,u5);
    r[3]=f2add(u6,u7); r[7]=f2sub(u6,u7);
}

// 8-point inverse DFT (unscaled), natural-order in/out.
__device__ __forceinline__ void idft8(float2* r) {
    float2 t0=f2add(r[0],r[4]), t4=f2sub(r[0],r[4]);
    float2 t1=f2add(r[1],r[5]), t5=f2sub(r[1],r[5]);
    float2 t2=f2add(r[2],r[6]), t6=f2sub(r[2],r[6]);
    float2 t3=f2add(r[3],r[7]), t7=f2sub(r[3],r[7]);
    t5 = make_float2( RSQ2*(t5.x-t5.y), RSQ2*(t5.x+t5.y));
    t6 = make_float2(-t6.y,  t6.x);
    t7 = make_float2(-RSQ2*(t7.x+t7.y), RSQ2*(t7.x-t7.y));
    float2 u0=f2add(t0,t2), u2=f2sub(t0,t2);
    float2 u1=f2add(t1,t3), u3=f2sub(t1,t3);
    float2 u4=f2add(t4,t6), u6=f2sub(t4,t6);
    float2 u5=f2add(t5,t7), u7=f2sub(t5,t7);
    u3 = make_float2(-u3.y, u3.x);
    u7 = make_float2(-u7.y, u7.x);
    r[0]=f2add(u0,u1); r[4]=f2sub(u0,u1);
    r[2]=f2add(u2,u3); r[6]=f2sub(u2,u3);
    r[1]=f2add(u4,u5); r[5]=f2sub(u4,u5);
    r[3]=f2add(u6,u7); r[7]=f2sub(u6,u7);
}

// storage idx = lt*8 + s with lt = m*8 + m'; frequency = m + 8*m' + 64*s.
__device__ __host__ __forceinline__ int dig512(int i) {
    return (i >> 6) + (((i >> 3) & 7) << 3) + ((i & 7) << 6);
}

// ---------------------------------------------------------------------------
__global__ void k_tw() {
    int t = threadIdx.x;  // 512 threads
    double ang = -2.0 * 3.141592653589793238462643 * (double)t / (double)N;
    double s, c;
    sincos(ang, &s, &c);
    g_tw[t] = make_float2((float)c, (float)s);
}

// Symmetrized filter Wsym[u,j] = mask[u,j]*(param(u,j)+param(-u,-j))/2,
// stored at [c][j true 0..256][dig^-1(u)], scaled by 1/(N*N).
__global__ void k_filter(const float* __restrict__ param) {
    int idx = blockIdx.x * blockDim.x + threadIdx.x;
    if (idx >= 3 * NJ * N) return;
    int iu  = idx & (N - 1);
    int rem = idx >> LOGN;
    int j   = rem % NJ;
    int c   = rem / NJ;
    int u = dig512(iu);
    int dh = (u <= N / 2) ? u : N - u;
    int dw = j;  // j in 0..256 -> min(j, 512-j) = j
    float m;
    if (dh * dh + dw * dw <= 1) {
        m = 0.5f;  // SMOOTHNESS
    } else {
        float dist = sqrtf((float)(dh * dh + dw * dw)) * (1.0f / 256.0f);
        m = fmaxf(1.0f, dist * 2.0f);
    }
    int is  = (u + 256) & (N - 1);
    int js  = (j + 256) & (N - 1);
    int is2 = (768 - u) & (N - 1);
    int js2 = (768 - j) & (N - 1);
    float p1 = param[((size_t)c * N + is) * N + js];
    float p2 = param[((size_t)c * N + is2) * N + js2];
    g_filt[idx] = m * 0.5f * (p1 + p2) * (1.0f / ((float)N * (float)N));
}

// ---------------------------------------------------------------------------
// K1: packed 2-real-row forward FFT. 256 threads = 4 groups x 64; group g
// handles rows (h0+2g, h0+2g+1) packed as z = x1 + i*x2. After the radix-8
// FFT, Z is staged by true frequency j in padded smem planes, unpacked to
// F1[h1,j], F1[h2,j] for j=0..256, and written transposed to g_spec[img][j][h].
// ---------------------------------------------------------------------------
__global__ void __launch_bounds__(256) k_rowfft(const float* __restrict__ x) {
    __shared__ float2 tw[N];
    __shared__ float2 ex[4 * 576];        // exchange bufs; reused as z planes
    __shared__ float2 tile[NJ * 9 + 3];   // [j*9 + hh]
    int t = threadIdx.x;
    tw[t] = g_tw[t];
    tw[t + 256] = g_tw[t + 256];

    int g = t >> 6, lt = t & 63;
    int img = blockIdx.y, h0 = blockIdx.x * 8;
    const float* xr1 = x + ((size_t)img * N + h0 + 2 * g) * N;
    const float* xr2 = xr1 + N;
    float2 r[8];
#pragma unroll
    for (int b = 0; b < 8; b++) r[b] = make_float2(xr1[lt + 64 * b], xr2[lt + 64 * b]);
    __syncthreads();

    float2* exg = ex + g * 576;

    // stage 1
    dft8(r);
#pragma unroll
    for (int m = 1; m < 8; m++) r[m] = cmul(tw[lt * m], r[m]);
#pragma unroll
    for (int m = 0; m < 8; m++) exg[m * 72 + lt] = r[m];
    __syncthreads();
    int m = lt >> 3, a2 = lt & 7;
#pragma unroll
    for (int b2 = 0; b2 < 8; b2++) r[b2] = exg[m * 72 + a2 + 8 * b2];

    // stage 2
    dft8(r);
#pragma unroll
    for (int mp = 1; mp < 8; mp++) r[mp] = cmul(tw[(a2 * mp) << 3], r[mp]);
    __syncthreads();
#pragma unroll
    for (int mp = 0; mp < 8; mp++) exg[m * 72 + mp * 9 + a2] = r[mp];
    __syncthreads();
    int mp = lt & 7;
#pragma unroll
    for (int a = 0; a < 8; a++) r[a] = exg[m * 72 + mp * 9 + a];

    // stage 3: r[s] = Z at frequency (m + 8*mp + 64*s)
    dft8(r);
    __syncthreads();  // all exchange reads done; reuse exg as z planes

    float* zre = (float*)exg;   // 528 floats
    float* zim = zre + 528;
    int base = m + 8 * mp;
#pragma unroll
    for (int s = 0; s < 8; s++) {
        int j = base + 64 * s;
        int zi = j + (j >> 5);
        zre[zi] = r[s].x;
        zim[zi] = r[s].y;
    }
    __syncthreads();

    // unpack: F1[h1,j] = (Z[j]+conj(Z[-j]))/2 ; F1[h2,j] = -i(Z[j]-conj(Z[-j]))/2
#pragma unroll
    for (int q = 0; q < 5; q++) {
        int j = lt + 64 * q;
        if (j <= 256) {
            int jm = (N - j) & (N - 1);
            int zi = j + (j >> 5), zmi = jm + (jm >> 5);
            float a = zre[zi], b = zim[zi];
            float c = zre[zmi], d = zim[zmi];
            tile[j * 9 + 2 * g]     = make_float2(0.5f * (a + c), 0.5f * (b - d));
            tile[j * 9 + 2 * g + 1] = make_float2(0.5f * (b + d), 0.5f * (c - a));
        }
    }
    __syncthreads();

    // transposed global write: 8 consecutive h per j (64B chunks)
    int hh = t & 7, jc = t >> 3;
    float2* dst = g_spec + (size_t)img * NJ * N + h0 + hh;
#pragma unroll
    for (int it = 0; it < 9; it++) {
        int j = jc + 32 * it;
        if (j < NJ) dst[(size_t)j * N] = tile[j * 9 + hh];
    }
}

// ---------------------------------------------------------------------------
// K2: column stage on 257 columns. 256 threads = 4 columns x 64. Per column:
// forward radix-8 FFT -> Wsym filter (coalesced float4) -> inverse radix-8.
// ---------------------------------------------------------------------------
__global__ void __launch_bounds__(256) k_colfft() {
    __shared__ float2 exs[4 * 576];
    __shared__ float2 tw[N];
    int t = threadIdx.x;
    tw[t] = g_tw[t];
    tw[t + 256] = g_tw[t + 256];

    int g = t >> 6, lt = t & 63;
    int jr = blockIdx.x * 4 + g;
    if (jr > 256) jr = 256;   // duplicate groups write identical values (benign)
    int img = blockIdx.y;
    int c = img % 3;
    float2* col = g_spec + ((size_t)img * NJ + jr) * N;
    float2* ex = exs + g * 576;

    float2 r[8];
#pragma unroll
    for (int b = 0; b < 8; b++) r[b] = col[lt + 64 * b];
    __syncthreads();

    // ---- forward ----
    dft8(r);
#pragma unroll
    for (int m = 1; m < 8; m++) r[m] = cmul(tw[lt * m], r[m]);
#pragma unroll
    for (int m = 0; m < 8; m++) ex[m * 72 + lt] = r[m];
    __syncthreads();
    int m = lt >> 3, a2 = lt & 7;
#pragma unroll
    for (int b2 = 0; b2 < 8; b2++) r[b2] = ex[m * 72 + a2 + 8 * b2];

    dft8(r);
#pragma unroll
    for (int mp = 1; mp < 8; mp++) r[mp] = cmul(tw[(a2 * mp) << 3], r[mp]);
    __syncthreads();
#pragma unroll
    for (int mp = 0; mp < 8; mp++) ex[m * 72 + mp * 9 + a2] = r[mp];
    __syncthreads();
    int mp = lt & 7;
#pragma unroll
    for (int a = 0; a < 8; a++) r[a] = ex[m * 72 + mp * 9 + a];

    dft8(r);   // storage idx = lt*8 + s

    // ---- filter ----
    const float* f = g_filt + ((size_t)c * NJ + jr) * N + lt * 8;
    float4 fa = *(const float4*)(f);
    float4 fb = *(const float4*)(f + 4);
    r[0].x *= fa.x; r[0].y *= fa.x;  r[1].x *= fa.y; r[1].y *= fa.y;
    r[2].x *= fa.z; r[2].y *= fa.z;  r[3].x *= fa.w; r[3].y *= fa.w;
    r[4].x *= fb.x; r[4].y *= fb.x;  r[5].x *= fb.y; r[5].y *= fb.y;
    r[6].x *= fb.z; r[6].y *= fb.z;  r[7].x *= fb.w; r[7].y *= fb.w;

    // ---- inverse ----
    idft8(r);
#pragma unroll
    for (int a = 1; a < 8; a++) r[a] = cmulc(tw[(a * mp) << 3], r[a]);
    __syncthreads();
#pragma unroll
    for (int a = 0; a < 8; a++) ex[m * 72 + mp * 9 + a] = r[a];
    __syncthreads();
#pragma unroll
    for (int mq = 0; mq < 8; mq++) r[mq] = ex[m * 72 + mq * 9 + a2];

    idft8(r);
#pragma unroll
    for (int b2 = 0; b2 < 8; b2++) r[b2] = cmulc(tw[(a2 + 8 * b2) * m], r[b2]);
    __syncthreads();
#pragma unroll
    for (int b2 = 0; b2 < 8; b2++) ex[m * 72 + a2 + 8 * b2] = r[b2];
    __syncthreads();
#pragma unroll
    for (int mq = 0; mq < 8; mq++) r[mq] = ex[mq * 72 + lt];

    idft8(r);   // natural h

#pragma unroll
    for (int b = 0; b < 8; b++) col[lt + 64 * b] = r[b];
}

// ---------------------------------------------------------------------------
// K3: row inverse, C2R via packing. Group g builds Z[j] = g1[h1,j] + i*g1[h2,j]
// (Hermitian extension for j>256) directly in storage order, runs the inverse
// radix-8 chain, and writes two real output rows.
// ---------------------------------------------------------------------------
__global__ void __launch_bounds__(256) k_rowifft(float* __restrict__ out) {
    __shared__ float2 tw[N];
    __shared__ float2 tile[NJ * 9 + 3];
    __shared__ float2 ex[4 * 576];
    int t = threadIdx.x;
    tw[t] = g_tw[t];
    tw[t + 256] = g_tw[t + 256];

    int img = blockIdx.y, h0 = blockIdx.x * 8;

    // coalesced transposed read of the half-spectrum for this block's 8 rows
    {
        int hh = t & 7, jc = t >> 3;
        const float2* src = g_spec + (size_t)img * NJ * N + h0 + hh;
#pragma unroll
        for (int it = 0; it < 9; it++) {
            int j = jc + 32 * it;
            if (j < NJ) tile[j * 9 + hh] = src[(size_t)j * N];
        }
    }
    __syncthreads();

    int g = t >> 6, lt = t & 63;
    int m = lt >> 3, mp = lt & 7, a2 = lt & 7;
    int base = m + 8 * mp;

    // build Z in storage order: r[s] = Z[base + 64*s]
    float2 r[8];
#pragma unroll
    for (int s = 0; s < 8; s++) {
        int j = base + 64 * s;
        if (j <= 256) {
            float2 f1 = tile[j * 9 + 2 * g];
            float2 f2 = tile[j * 9 + 2 * g + 1];
            r[s] = make_float2(f1.x - f2.y, f1.y + f2.x);        // g1h1 + i*g1h2
        } else {
            int jm = N - j;
            float2 f1 = tile[jm * 9 + 2 * g];
            float2 f2 = tile[jm * 9 + 2 * g + 1];
            r[s] = make_float2(f1.x + f2.y, f2.x - f1.y);        // conj(g1h1)+i*conj(g1h2)
        }
    }

    float2* exg = ex + g * 576;

    idft8(r);
#pragma unroll
    for (int a = 1; a < 8; a++) r[a] = cmulc(tw[(a * mp) << 3], r[a]);
    __syncthreads();
#pragma unroll
    for (int a = 0; a < 8; a++) exg[m * 72 + mp * 9 + a] = r[a];
    __syncthreads();
#pragma unroll
    for (int mq = 0; mq < 8; mq++) r[mq] = exg[m * 72 + mq * 9 + a2];

    idft8(r);
#pragma unroll
    for (int b2 = 0; b2 < 8; b2++) r[b2] = cmulc(tw[(a2 + 8 * b2) * m], r[b2]);
    __syncthreads();
#pragma unroll
    for (int b2 = 0; b2 < 8; b2++) exg[m * 72 + a2 + 8 * b2] = r[b2];
    __syncthreads();
#pragma unroll
    for (int mq = 0; mq < 8; mq++) r[mq] = exg[mq * 72 + lt];

    idft8(r);   // natural w; r = out[h1,w] + i*out[h2,w]

    float* o1 = out + ((size_t)img * N + h0 + 2 * g) * N;
    float* o2 = o1 + N;
#pragma unroll
    for (int b = 0; b < 8; b++) {
        o1[lt + 64 * b] = r[b].x;
        o2[lt + 64 * b] = r[b].y;
    }
}

// ---------------------------------------------------------------------------
extern "C" void kernel_launch(void* const* d_in, const int* in_sizes, int n_in,
                              void* d_out, int out_size) {
    int ix = 0, ip = 1;
    if (n_in >= 2 && in_sizes[0] == 3 * N * N) { ix = 1; ip = 0; }
    const float* x     = (const float*)d_in[ix];
    const float* param = (const float*)d_in[ip];
    float* out = (float*)d_out;

    k_tw<<<1, 512>>>();
    k_filter<<<(3 * NJ * N + 255) / 256, 256>>>(param);
    k_rowfft<<<dim3(N / 8, NIMG), 256>>>(x);
    k_colfft<<<dim3((NJ + 3) / 4, NIMG), 256>>>();
    k_rowifft<<<dim3(N / 8, NIMG), 256>>>(out);
}

// round 15
// speedup vs baseline: 1.3818x; 1.3818x over previous
#include <cuda_runtime.h>
#include <math.h>

// Problem constants
#define N      512
#define LOGN   9
#define NIMG   96          // 32 batch * 3 channels
#define NJ     257         // stored half-spectrum columns (0..256)

// Scratch (device globals: allocation-free rule)
__device__ float2 g_spec[(size_t)NIMG * NJ * N];  // [img][j 0..256][h]
__device__ float  g_filt[(size_t)3 * NJ * N];     // [c][j][iu_store] (u digit-reversed)
__device__ float2 g_tw[N];                        // W_512^k

#define RSQ2 0.70710678118654752440f

// 64-thread group barrier (named barrier per FFT group)
#define GBAR(id) asm volatile("bar.sync %0, 64;" :: "r"(id) : "memory")

__device__ __forceinline__ float2 f2add(float2 a, float2 b){ return make_float2(a.x+b.x, a.y+b.y); }
__device__ __forceinline__ float2 f2sub(float2 a, float2 b){ return make_float2(a.x-b.x, a.y-b.y); }
__device__ __forceinline__ float2 cj(float2 a){ return make_float2(a.x, -a.y); }
__device__ __forceinline__ float2 cmul(float2 a, float2 b){           // a*b
    return make_float2(a.x*b.x - a.y*b.y, a.x*b.y + a.y*b.x);
}

// w[i] = w1^(i+1), computed with depth-3 chain (FMA pipe, no smem)
__device__ __forceinline__ void twpow7(float2 w1, float2* w) {
    w[0] = w1;
    w[1] = cmul(w1, w1);
    w[2] = cmul(w[1], w1);
    w[3] = cmul(w[1], w[1]);
    w[4] = cmul(w[2], w[1]);
    w[5] = cmul(w[2], w[2]);
    w[6] = cmul(w[3], w[2]);
}

// 8-point DFT, natural-order in/out, in registers.
__device__ __forceinline__ void dft8(float2* r) {
    float2 t0=f2add(r[0],r[4]), t4=f2sub(r[0],r[4]);
    float2 t1=f2add(r[1],r[5]), t5=f2sub(r[1],r[5]);
    float2 t2=f2add(r[2],r[6]), t6=f2sub(r[2],r[6]);
    float2 t3=f2add(r[3],r[7]), t7=f2sub(r[3],r[7]);
    t5 = make_float2(RSQ2*(t5.x+t5.y),  RSQ2*(t5.y-t5.x));
    t6 = make_float2(t6.y, -t6.x);
    t7 = make_float2(RSQ2*(t7.y-t7.x), -RSQ2*(t7.x+t7.y));
    float2 u0=f2add(t0,t2), u2=f2sub(t0,t2);
    float2 u1=f2add(t1,t3), u3=f2sub(t1,t3);
    float2 u4=f2add(t4,t6), u6=f2sub(t4,t6);
    float2 u5=f2add(t5,t7), u7=f2sub(t5,t7);
    u3 = make_float2(u3.y, -u3.x);
    u7 = make_float2(u7.y, -u7.x);
    r[0]=f2add(u0,u1); r[4]=f2sub(u0,u1);
    r[2]=f2add(u2,u3); r[6]=f2sub(u2,u3);
    r[1]=f2add(u4,u5); r[5]=f2sub(u4,u5);
    r[3]=f2add(u6,u7); r[7]=f2sub(u6,u7);
}

// 8-point inverse DFT (unscaled), natural-order in/out.
__device__ __forceinline__ void idft8(float2* r) {
    float2 t0=f2add(r[0],r[4]), t4=f2sub(r[0],r[4]);
    float2 t1=f2add(r[1],r[5]), t5=f2sub(r[1],r[5]);
    float2 t2=f2add(r[2],r[6]), t6=f2sub(r[2],r[6]);
    float2 t3=f2add(r[3],r[7]), t7=f2sub(r[3],r[7]);
    t5 = make_float2( RSQ2*(t5.x-t5.y), RSQ2*(t5.x+t5.y));
    t6 = make_float2(-t6.y,  t6.x);
    t7 = make_float2(-RSQ2*(t7.x+t7.y), RSQ2*(t7.x-t7.y));
    float2 u0=f2add(t0,t2), u2=f2sub(t0,t2);
    float2 u1=f2add(t1,t3), u3=f2sub(t1,t3);
    float2 u4=f2add(t4,t6), u6=f2sub(t4,t6);
    float2 u5=f2add(t5,t7), u7=f2sub(t5,t7);
    u3 = make_float2(-u3.y, u3.x);
    u7 = make_float2(-u7.y, u7.x);
    r[0]=f2add(u0,u1); r[4]=f2sub(u0,u1);
    r[2]=f2add(u2,u3); r[6]=f2sub(u2,u3);
    r[1]=f2add(u4,u5); r[5]=f2sub(u4,u5);
    r[3]=f2add(u6,u7); r[7]=f2sub(u6,u7);
}

// storage idx = lt*8 + s with lt = m*8 + m'; frequency = m + 8*m' + 64*s.
__device__ __host__ __forceinline__ int dig512(int i) {
    return (i >> 6) + (((i >> 3) & 7) << 3) + ((i & 7) << 6);
}

// inverse stage-B twiddles: T[b2] = conj(W^((a2+8*b2)*m)), applied to r[0..7]
__device__ __forceinline__ void inv_twB(float2* r, int a2, int m) {
    float2 t0 = cj(__ldg(&g_tw[a2 * m]));
    float2 c1 = cj(__ldg(&g_tw[m << 3]));
    float2 c2 = cmul(c1, c1);
    float2 c4 = cmul(c2, c2);
    float2 T1 = cmul(t0, c1);
    float2 T2 = cmul(t0, c2);
    float2 T3 = cmul(T1, c2);
    r[0] = cmul(t0, r[0]);
    r[1] = cmul(T1, r[1]);
    r[2] = cmul(T2, r[2]);
    r[3] = cmul(T3, r[3]);
    r[4] = cmul(cmul(t0, c4), r[4]);
    r[5] = cmul(cmul(T1, c4), r[5]);
    r[6] = cmul(cmul(T2, c4), r[6]);
    r[7] = cmul(cmul(T3, c4), r[7]);
}

// ---------------------------------------------------------------------------
__global__ void k_tw() {
    int t = threadIdx.x;  // 512 threads
    double ang = -2.0 * 3.141592653589793238462643 * (double)t / (double)N;
    double s, c;
    sincos(ang, &s, &c);
    g_tw[t] = make_float2((float)c, (float)s);
}

// Symmetrized filter Wsym[u,j] = mask[u,j]*(param(u,j)+param(-u,-j))/2,
// stored at [c][j true 0..256][dig^-1(u)], scaled by 1/(N*N).
__global__ void k_filter(const float* __restrict__ param) {
    int idx = blockIdx.x * blockDim.x + threadIdx.x;
    if (idx >= 3 * NJ * N) return;
    int iu  = idx & (N - 1);
    int rem = idx >> LOGN;
    int j   = rem % NJ;
    int c   = rem / NJ;
    int u = dig512(iu);
    int dh = (u <= N / 2) ? u : N - u;
    int dw = j;
    float m;
    if (dh * dh + dw * dw <= 1) {
        m = 0.5f;  // SMOOTHNESS
    } else {
        float dist = sqrtf((float)(dh * dh + dw * dw)) * (1.0f / 256.0f);
        m = fmaxf(1.0f, dist * 2.0f);
    }
    int is  = (u + 256) & (N - 1);
    int js  = (j + 256) & (N - 1);
    int is2 = (768 - u) & (N - 1);
    int js2 = (768 - j) & (N - 1);
    float p1 = param[((size_t)c * N + is) * N + js];
    float p2 = param[((size_t)c * N + is2) * N + js2];
    g_filt[idx] = m * 0.5f * (p1 + p2) * (1.0f / ((float)N * (float)N));
}

// ---------------------------------------------------------------------------
// K1: packed 2-real-row forward FFT. 256 threads = 4 groups x 64.
// Twiddles computed in registers; per-group named barriers for exchanges.
// ---------------------------------------------------------------------------
__global__ void __launch_bounds__(256) k_rowfft(const float* __restrict__ x) {
    __shared__ float2 ex[4 * 576];        // exchange bufs; reused as z planes
    __shared__ float2 tile[NJ * 9 + 3];   // [j*9 + hh]
    int t = threadIdx.x;
    int g = t >> 6, lt = t & 63;
    int bar = g + 1;
    int m = lt >> 3, a2 = lt & 7;
    int img = blockIdx.y, h0 = blockIdx.x * 8;

    const float* xr1 = x + ((size_t)img * N + h0 + 2 * g) * N;
    const float* xr2 = xr1 + N;
    float2 r[8];
#pragma unroll
    for (int b = 0; b < 8; b++) r[b] = make_float2(xr1[lt + 64 * b], xr2[lt + 64 * b]);

    float2* exg = ex + g * 576;

    // stage 1
    dft8(r);
    {
        float2 w[7];
        twpow7(__ldg(&g_tw[lt]), w);
#pragma unroll
        for (int i = 0; i < 7; i++) r[i + 1] = cmul(w[i], r[i + 1]);
    }
#pragma unroll
    for (int mm = 0; mm < 8; mm++) exg[mm * 72 + lt] = r[mm];
    GBAR(bar);
#pragma unroll
    for (int b2 = 0; b2 < 8; b2++) r[b2] = exg[m * 72 + a2 + 8 * b2];
    GBAR(bar);

    // stage 2
    dft8(r);
    {
        float2 w[7];
        twpow7(__ldg(&g_tw[a2 << 3]), w);
#pragma unroll
        for (int i = 0; i < 7; i++) r[i + 1] = cmul(w[i], r[i + 1]);
    }
#pragma unroll
    for (int mp = 0; mp < 8; mp++) exg[m * 72 + mp * 9 + a2] = r[mp];
    GBAR(bar);
#pragma unroll
    for (int a = 0; a < 8; a++) r[a] = exg[m * 72 + a2 * 9 + a];

    // stage 3: r[s] = Z at frequency (m + 8*a2 + 64*s)
    dft8(r);
    GBAR(bar);  // exchange reads done; reuse exg as z planes

    float* zre = (float*)exg;   // 528 floats
    float* zim = zre + 528;
    int base = m + 8 * a2;
#pragma unroll
    for (int s = 0; s < 8; s++) {
        int j = base + 64 * s;
        int zi = j + (j >> 5);
        zre[zi] = r[s].x;
        zim[zi] = r[s].y;
    }
    GBAR(bar);

    // unpack: F1[h1,j] = (Z[j]+conj(Z[-j]))/2 ; F1[h2,j] = -i(Z[j]-conj(Z[-j]))/2
#pragma unroll
    for (int q = 0; q < 5; q++) {
        int j = lt + 64 * q;
        if (j <= 256) {
            int jm = (N - j) & (N - 1);
            int zi = j + (j >> 5), zmi = jm + (jm >> 5);
            float a = zre[zi], b = zim[zi];
            float c = zre[zmi], d = zim[zmi];
            tile[j * 9 + 2 * g]     = make_float2(0.5f * (a + c), 0.5f * (b - d));
            tile[j * 9 + 2 * g + 1] = make_float2(0.5f * (b + d), 0.5f * (c - a));
        }
    }
    __syncthreads();   // tile is cross-group

    // transposed global write: 8 consecutive h per j (64B chunks)
    int hh = t & 7, jc = t >> 3;
    float2* dst = g_spec + (size_t)img * NJ * N + h0 + hh;
#pragma unroll
    for (int it = 0; it < 9; it++) {
        int j = jc + 32 * it;
        if (j < NJ) dst[(size_t)j * N] = tile[j * 9 + hh];
    }
}

// ---------------------------------------------------------------------------
// K2: column stage on 257 columns. 256 threads = 4 columns x 64.
// ---------------------------------------------------------------------------
__global__ void __launch_bounds__(256) k_colfft() {
    __shared__ float2 exs[4 * 576];
    int t = threadIdx.x;
    int g = t >> 6, lt = t & 63;
    int bar = g + 1;
    int m = lt >> 3, a2 = lt & 7;
    int jr = blockIdx.x * 4 + g;
    if (jr > 256) jr = 256;   // duplicate groups write identical values (benign)
    int img = blockIdx.y;
    int c = img % 3;
    float2* col = g_spec + ((size_t)img * NJ + jr) * N;
    float2* ex = exs + g * 576;

    float2 r[8];
#pragma unroll
    for (int b = 0; b < 8; b++) r[b] = col[lt + 64 * b];

    // ---- forward ----
    dft8(r);
    {
        float2 w[7];
        twpow7(__ldg(&g_tw[lt]), w);
#pragma unroll
        for (int i = 0; i < 7; i++) r[i + 1] = cmul(w[i], r[i + 1]);
    }
#pragma unroll
    for (int mm = 0; mm < 8; mm++) ex[mm * 72 + lt] = r[mm];
    GBAR(bar);
#pragma unroll
    for (int b2 = 0; b2 < 8; b2++) r[b2] = ex[m * 72 + a2 + 8 * b2];
    GBAR(bar);

    dft8(r);
    {
        float2 w[7];
        twpow7(__ldg(&g_tw[a2 << 3]), w);
#pragma unroll
        for (int i = 0; i < 7; i++) r[i + 1] = cmul(w[i], r[i + 1]);
    }
#pragma unroll
    for (int mp = 0; mp < 8; mp++) ex[m * 72 + mp * 9 + a2] = r[mp];
    GBAR(bar);
#pragma unroll
    for (int a = 0; a < 8; a++) r[a] = ex[m * 72 + a2 * 9 + a];

    dft8(r);   // storage idx = lt*8 + s

    // ---- filter (coalesced: two float4 per thread) ----
    const float* f = g_filt + ((size_t)c * NJ + jr) * N + lt * 8;
    float4 fa = *(const float4*)(f);
    float4 fb = *(const float4*)(f + 4);
    r[0].x *= fa.x; r[0].y *= fa.x;  r[1].x *= fa.y; r[1].y *= fa.y;
    r[2].x *= fa.z; r[2].y *= fa.z;  r[3].x *= fa.w; r[3].y *= fa.w;
    r[4].x *= fb.x; r[4].y *= fb.x;  r[5].x *= fb.y; r[5].y *= fb.y;
    r[6].x *= fb.z; r[6].y *= fb.z;  r[7].x *= fb.w; r[7].y *= fb.w;

    // ---- inverse ----
    idft8(r);
    {
        float2 w[7];
        twpow7(cj(__ldg(&g_tw[a2 << 3])), w);   // mp == a2
#pragma unroll
        for (int i = 0; i < 7; i++) r[i + 1] = cmul(w[i], r[i + 1]);
    }
    GBAR(bar);   // WAR: fwd stage-2 reads done in all group threads
#pragma unroll
    for (int a = 0; a < 8; a++) ex[m * 72 + a2 * 9 + a] = r[a];
    GBAR(bar);
#pragma unroll
    for (int mq = 0; mq < 8; mq++) r[mq] = ex[m * 72 + mq * 9 + a2];
    GBAR(bar);

    idft8(r);
    inv_twB(r, a2, m);
#pragma unroll
    for (int b2 = 0; b2 < 8; b2++) ex[m * 72 + a2 + 8 * b2] = r[b2];
    GBAR(bar);
#pragma unroll
    for (int mq = 0; mq < 8; mq++) r[mq] = ex[mq * 72 + lt];

    idft8(r);   // natural h

#pragma unroll
    for (int b = 0; b < 8; b++) col[lt + 64 * b] = r[b];
}

// ---------------------------------------------------------------------------
// K3: row inverse, C2R via packing.
// ---------------------------------------------------------------------------
__global__ void __launch_bounds__(256) k_rowifft(float* __restrict__ out) {
    __shared__ float2 tile[NJ * 9 + 3];
    __shared__ float2 ex[4 * 576];
    int t = threadIdx.x;
    int img = blockIdx.y, h0 = blockIdx.x * 8;

    // coalesced transposed read of the half-spectrum for this block's 8 rows
    {
        int hh = t & 7, jc = t >> 3;
        const float2* src = g_spec + (size_t)img * NJ * N + h0 + hh;
#pragma unroll
        for (int it = 0; it < 9; it++) {
            int j = jc + 32 * it;
            if (j < NJ) tile[j * 9 + hh] = src[(size_t)j * N];
        }
    }
    __syncthreads();

    int g = t >> 6, lt = t & 63;
    int bar = g + 1;
    int m = lt >> 3, a2 = lt & 7;
    int base = m + 8 * a2;

    // build Z in storage order: r[s] = Z[base + 64*s]
    float2 r[8];
#pragma unroll
    for (int s = 0; s < 8; s++) {
        int j = base + 64 * s;
        if (j <= 256) {
            float2 f1 = tile[j * 9 + 2 * g];
            float2 f2 = tile[j * 9 + 2 * g + 1];
            r[s] = make_float2(f1.x - f2.y, f1.y + f2.x);        // g1h1 + i*g1h2
        } else {
            int jm = N - j;
            float2 f1 = tile[jm * 9 + 2 * g];
            float2 f2 = tile[jm * 9 + 2 * g + 1];
            r[s] = make_float2(f1.x + f2.y, f2.x - f1.y);        // conj(g1h1)+i*conj(g1h2)
        }
    }

    float2* exg = ex + g * 576;

    idft8(r);
    {
        float2 w[7];
        twpow7(cj(__ldg(&g_tw[a2 << 3])), w);   // mp == a2
#pragma unroll
        for (int i = 0; i < 7; i++) r[i + 1] = cmul(w[i], r[i + 1]);
    }
#pragma unroll
    for (int a = 0; a < 8; a++) exg[m * 72 + a2 * 9 + a] = r[a];
    GBAR(bar);
#pragma unroll
    for (int mq = 0; mq < 8; mq++) r[mq] = exg[m * 72 + mq * 9 + a2];
    GBAR(bar);

    idft8(r);
    inv_twB(r, a2, m);
#pragma unroll
    for (int b2 = 0; b2 < 8; b2++) exg[m * 72 + a2 + 8 * b2] = r[b2];
    GBAR(bar);
#pragma unroll
    for (int mq = 0; mq < 8; mq++) r[mq] = exg[mq * 72 + lt];

    idft8(r);   // natural w; r = out[h1,w] + i*out[h2,w]

    float* o1 = out + ((size_t)img * N + h0 + 2 * g) * N;
    float* o2 = o1 + N;
#pragma unroll
    for (int b = 0; b < 8; b++) {
        o1[lt + 64 * b] = r[b].x;
        o2[lt + 64 * b] = r[b].y;
    }
}

// ---------------------------------------------------------------------------
extern "C" void kernel_launch(void* const* d_in, const int* in_sizes, int n_in,
                              void* d_out, int out_size) {
    int ix = 0, ip = 1;
    if (n_in >= 2 && in_sizes[0] == 3 * N * N) { ix = 1; ip = 0; }
    const float* x     = (const float*)d_in[ix];
    const float* param = (const float*)d_in[ip];
    float* out = (float*)d_out;

    k_tw<<<1, 512>>>();
    k_filter<<<(3 * NJ * N + 255) / 256, 256>>>(param);
    k_rowfft<<<dim3(N / 8, NIMG), 256>>>(x);
    k_colfft<<<dim3((NJ + 3) / 4, NIMG), 256>>>();
    k_rowifft<<<dim3(N / 8, NIMG), 256>>>(out);
}

// round 16
// speedup vs baseline: 1.7487x; 1.2656x over previous
#include <cuda_runtime.h>
#include <cuda_fp16.h>
#include <math.h>

// Problem constants
#define N      512
#define LOGN   9
#define NIMG   96          // 32 batch * 3 channels
#define NJ     257         // stored half-spectrum columns (0..256)

// Scratch (device globals: allocation-free rule)
__device__ __half2 g_spec[(size_t)NIMG * NJ * N];  // [img][j 0..256][h], fp16 storage
__device__ float   g_filt[(size_t)3 * NJ * N];     // [c][j][iu_store] (u digit-reversed)
__device__ float2  g_tw[N];                        // W_512^k

#define RSQ2 0.70710678118654752440f

// 64-thread group barrier (named barrier per FFT group)
#define GBAR(id) asm volatile("bar.sync %0, 64;" :: "r"(id) : "memory")

typedef unsigned long long u64_t;

// Packed f32x2 ops (sm_103a) — ptxas never auto-packs these.
__device__ __forceinline__ float2 f2add(float2 a, float2 b){
    float2 r;
    asm("add.rn.f32x2 %0, %1, %2;"
        : "=l"(*(u64_t*)&r) : "l"(*(u64_t*)&a), "l"(*(u64_t*)&b));
    return r;
}
__device__ __forceinline__ float2 f2sub(float2 a, float2 b){
    float2 r;
    asm("sub.rn.f32x2 %0, %1, %2;"
        : "=l"(*(u64_t*)&r) : "l"(*(u64_t*)&a), "l"(*(u64_t*)&b));
    return r;
}
__device__ __forceinline__ float2 f2mul(float2 a, float2 b){
    float2 r;
    asm("mul.rn.f32x2 %0, %1, %2;"
        : "=l"(*(u64_t*)&r) : "l"(*(u64_t*)&a), "l"(*(u64_t*)&b));
    return r;
}

__device__ __forceinline__ float2 cj(float2 a){ return make_float2(a.x, -a.y); }
__device__ __forceinline__ float2 cmul(float2 a, float2 b){           // a*b
    return make_float2(a.x*b.x - a.y*b.y, a.x*b.y + a.y*b.x);
}

__device__ __forceinline__ float2  h2f(__half2 h){ return __half22float2(h); }
__device__ __forceinline__ __half2 f2h(float2 f){ return __floats2half2_rn(f.x, f.y); }

// w[i] = w1^(i+1), computed with depth-3 chain (FMA pipe, no smem)
__device__ __forceinline__ void twpow7(float2 w1, float2* w) {
    w[0] = w1;
    w[1] = cmul(w1, w1);
    w[2] = cmul(w[1], w1);
    w[3] = cmul(w[1], w[1]);
    w[4] = cmul(w[2], w[1]);
    w[5] = cmul(w[2], w[2]);
    w[6] = cmul(w[3], w[2]);
}

// 8-point DFT, natural-order in/out, in registers (packed adds).
__device__ __forceinline__ void dft8(float2* r) {
    const float2 RS = make_float2(RSQ2, RSQ2);
    float2 t0=f2add(r[0],r[4]), t4=f2sub(r[0],r[4]);
    float2 t1=f2add(r[1],r[5]), t5=f2sub(r[1],r[5]);
    float2 t2=f2add(r[2],r[6]), t6=f2sub(r[2],r[6]);
    float2 t3=f2add(r[3],r[7]), t7=f2sub(r[3],r[7]);
    t5 = f2mul(make_float2(t5.x + t5.y,  t5.y - t5.x), RS);   // *W8^1
    t6 = make_float2(t6.y, -t6.x);                            // *(-i)
    t7 = f2mul(make_float2(t7.y - t7.x, -(t7.x + t7.y)), RS); // *W8^3
    float2 u0=f2add(t0,t2), u2=f2sub(t0,t2);
    float2 u1=f2add(t1,t3), u3=f2sub(t1,t3);
    float2 u4=f2add(t4,t6), u6=f2sub(t4,t6);
    float2 u5=f2add(t5,t7), u7=f2sub(t5,t7);
    u3 = make_float2(u3.y, -u3.x);
    u7 = make_float2(u7.y, -u7.x);
    r[0]=f2add(u0,u1); r[4]=f2sub(u0,u1);
    r[2]=f2add(u2,u3); r[6]=f2sub(u2,u3);
    r[1]=f2add(u4,u5); r[5]=f2sub(u4,u5);
    r[3]=f2add(u6,u7); r[7]=f2sub(u6,u7);
}

// 8-point inverse DFT (unscaled), natural-order in/out (packed adds).
__device__ __forceinline__ void idft8(float2* r) {
    const float2 RS = make_float2(RSQ2, RSQ2);
    float2 t0=f2add(r[0],r[4]), t4=f2sub(r[0],r[4]);
    float2 t1=f2add(r[1],r[5]), t5=f2sub(r[1],r[5]);
    float2 t2=f2add(r[2],r[6]), t6=f2sub(r[2],r[6]);
    float2 t3=f2add(r[3],r[7]), t7=f2sub(r[3],r[7]);
    t5 = f2mul(make_float2(t5.x - t5.y,  t5.x + t5.y), RS);   // *conj(W8^1)
    t6 = make_float2(-t6.y,  t6.x);                           // *(+i)
    t7 = f2mul(make_float2(-(t7.x + t7.y), t7.x - t7.y), RS); // *conj(W8^3)
    float2 u0=f2add(t0,t2), u2=f2sub(t0,t2);
    float2 u1=f2add(t1,t3), u3=f2sub(t1,t3);
    float2 u4=f2add(t4,t6), u6=f2sub(t4,t6);
    float2 u5=f2add(t5,t7), u7=f2sub(t5,t7);
    u3 = make_float2(-u3.y, u3.x);
    u7 = make_float2(-u7.y, u7.x);
    r[0]=f2add(u0,u1); r[4]=f2sub(u0,u1);
    r[2]=f2add(u2,u3); r[6]=f2sub(u2,u3);
    r[1]=f2add(u4,u5); r[5]=f2sub(u4,u5);
    r[3]=f2add(u6,u7); r[7]=f2sub(u6,u7);
}

// storage idx = lt*8 + s with lt = m*8 + m'; frequency = m + 8*m' + 64*s.
__device__ __host__ __forceinline__ int dig512(int i) {
    return (i >> 6) + (((i >> 3) & 7) << 3) + ((i & 7) << 6);
}

// inverse stage-B twiddles: T[b2] = conj(W^((a2+8*b2)*m)), applied to r[0..7]
__device__ __forceinline__ void inv_twB(float2* r, int a2, int m) {
    float2 t0 = cj(__ldg(&g_tw[a2 * m]));
    float2 c1 = cj(__ldg(&g_tw[m << 3]));
    float2 c2 = cmul(c1, c1);
    float2 c4 = cmul(c2, c2);
    float2 T1 = cmul(t0, c1);
    float2 T2 = cmul(t0, c2);
    float2 T3 = cmul(T1, c2);
    r[0] = cmul(t0, r[0]);
    r[1] = cmul(T1, r[1]);
    r[2] = cmul(T2, r[2]);
    r[3] = cmul(T3, r[3]);
    r[4] = cmul(cmul(t0, c4), r[4]);
    r[5] = cmul(cmul(T1, c4), r[5]);
    r[6] = cmul(cmul(T2, c4), r[6]);
    r[7] = cmul(cmul(T3, c4), r[7]);
}

// ---------------------------------------------------------------------------
__global__ void k_tw() {
    int t = threadIdx.x;  // 512 threads
    double ang = -2.0 * 3.141592653589793238462643 * (double)t / (double)N;
    double s, c;
    sincos(ang, &s, &c);
    g_tw[t] = make_float2((float)c, (float)s);
}

// Symmetrized filter Wsym[u,j] = mask[u,j]*(param(u,j)+param(-u,-j))/2,
// stored at [c][j true 0..256][dig^-1(u)], scaled by 1/(N*N).
__global__ void k_filter(const float* __restrict__ param) {
    int idx = blockIdx.x * blockDim.x + threadIdx.x;
    if (idx >= 3 * NJ * N) return;
    int iu  = idx & (N - 1);
    int rem = idx >> LOGN;
    int j   = rem % NJ;
    int c   = rem / NJ;
    int u = dig512(iu);
    int dh = (u <= N / 2) ? u : N - u;
    int dw = j;
    float m;
    if (dh * dh + dw * dw <= 1) {
        m = 0.5f;  // SMOOTHNESS
    } else {
        float dist = sqrtf((float)(dh * dh + dw * dw)) * (1.0f / 256.0f);
        m = fmaxf(1.0f, dist * 2.0f);
    }
    int is  = (u + 256) & (N - 1);
    int js  = (j + 256) & (N - 1);
    int is2 = (768 - u) & (N - 1);
    int js2 = (768 - j) & (N - 1);
    float p1 = param[((size_t)c * N + is) * N + js];
    float p2 = param[((size_t)c * N + is2) * N + js2];
    g_filt[idx] = m * 0.5f * (p1 + p2) * (1.0f / ((float)N * (float)N));
}

// ---------------------------------------------------------------------------
// K1: packed 2-real-row forward FFT. 256 threads = 4 groups x 64.
// ---------------------------------------------------------------------------
__global__ void __launch_bounds__(256) k_rowfft(const float* __restrict__ x) {
    __shared__ float2 ex[4 * 576];          // exchange bufs; reused as z planes
    __shared__ __half2 tile[NJ * 9 + 3];    // [j*9 + hh], fp16
    int t = threadIdx.x;
    int g = t >> 6, lt = t & 63;
    int bar = g + 1;
    int m = lt >> 3, a2 = lt & 7;
    int img = blockIdx.y, h0 = blockIdx.x * 8;

    const float* xr1 = x + ((size_t)img * N + h0 + 2 * g) * N;
    const float* xr2 = xr1 + N;
    float2 r[8];
#pragma unroll
    for (int b = 0; b < 8; b++) r[b] = make_float2(xr1[lt + 64 * b], xr2[lt + 64 * b]);

    float2* exg = ex + g * 576;

    // stage 1
    dft8(r);
    {
        float2 w[7];
        twpow7(__ldg(&g_tw[lt]), w);
#pragma unroll
        for (int i = 0; i < 7; i++) r[i + 1] = cmul(w[i], r[i + 1]);
    }
#pragma unroll
    for (int mm = 0; mm < 8; mm++) exg[mm * 72 + lt] = r[mm];
    GBAR(bar);
#pragma unroll
    for (int b2 = 0; b2 < 8; b2++) r[b2] = exg[m * 72 + a2 + 8 * b2];
    GBAR(bar);

    // stage 2
    dft8(r);
    {
        float2 w[7];
        twpow7(__ldg(&g_tw[a2 << 3]), w);
#pragma unroll
        for (int i = 0; i < 7; i++) r[i + 1] = cmul(w[i], r[i + 1]);
    }
#pragma unroll
    for (int mp = 0; mp < 8; mp++) exg[m * 72 + mp * 9 + a2] = r[mp];
    GBAR(bar);
#pragma unroll
    for (int a = 0; a < 8; a++) r[a] = exg[m * 72 + a2 * 9 + a];

    // stage 3: r[s] = Z at frequency (m + 8*a2 + 64*s)
    dft8(r);
    GBAR(bar);  // exchange reads done; reuse exg as z planes

    float* zre = (float*)exg;   // 528 floats
    float* zim = zre + 528;
    int base = m + 8 * a2;
#pragma unroll
    for (int s = 0; s < 8; s++) {
        int j = base + 64 * s;
        int zi = j + (j >> 5);
        zre[zi] = r[s].x;
        zim[zi] = r[s].y;
    }
    GBAR(bar);

    // unpack: F1[h1,j] = (Z[j]+conj(Z[-j]))/2 ; F1[h2,j] = -i(Z[j]-conj(Z[-j]))/2
#pragma unroll
    for (int q = 0; q < 5; q++) {
        int j = lt + 64 * q;
        if (j <= 256) {
            int jm = (N - j) & (N - 1);
            int zi = j + (j >> 5), zmi = jm + (jm >> 5);
            float a = zre[zi], b = zim[zi];
            float c = zre[zmi], d = zim[zmi];
            tile[j * 9 + 2 * g]     = f2h(make_float2(0.5f * (a + c), 0.5f * (b - d)));
            tile[j * 9 + 2 * g + 1] = f2h(make_float2(0.5f * (b + d), 0.5f * (c - a)));
        }
    }
    __syncthreads();   // tile is cross-group

    // transposed global write: 8 consecutive h per j (32B chunks)
    int hh = t & 7, jc = t >> 3;
    __half2* dst = g_spec + (size_t)img * NJ * N + h0 + hh;
#pragma unroll
    for (int it = 0; it < 9; it++) {
        int j = jc + 32 * it;
        if (j < NJ) dst[(size_t)j * N] = tile[j * 9 + hh];
    }
}

// ---------------------------------------------------------------------------
// K2: column stage on 257 columns. 256 threads = 4 columns x 64.
// ---------------------------------------------------------------------------
__global__ void __launch_bounds__(256) k_colfft() {
    __shared__ float2 exs[4 * 576];
    int t = threadIdx.x;
    int g = t >> 6, lt = t & 63;
    int bar = g + 1;
    int m = lt >> 3, a2 = lt & 7;
    int jr = blockIdx.x * 4 + g;
    if (jr > 256) jr = 256;   // duplicate groups write identical values (benign)
    int img = blockIdx.y;
    int c = img % 3;
    __half2* col = g_spec + ((size_t)img * NJ + jr) * N;
    float2* ex = exs + g * 576;

    float2 r[8];
#pragma unroll
    for (int b = 0; b < 8; b++) r[b] = h2f(col[lt + 64 * b]);

    // ---- forward ----
    dft8(r);
    {
        float2 w[7];
        twpow7(__ldg(&g_tw[lt]), w);
#pragma unroll
        for (int i = 0; i < 7; i++) r[i + 1] = cmul(w[i], r[i + 1]);
    }
#pragma unroll
    for (int mm = 0; mm < 8; mm++) ex[mm * 72 + lt] = r[mm];
    GBAR(bar);
#pragma unroll
    for (int b2 = 0; b2 < 8; b2++) r[b2] = ex[m * 72 + a2 + 8 * b2];
    GBAR(bar);

    dft8(r);
    {
        float2 w[7];
        twpow7(__ldg(&g_tw[a2 << 3]), w);
#pragma unroll
        for (int i = 0; i < 7; i++) r[i + 1] = cmul(w[i], r[i + 1]);
    }
#pragma unroll
    for (int mp = 0; mp < 8; mp++) ex[m * 72 + mp * 9 + a2] = r[mp];
    GBAR(bar);
#pragma unroll
    for (int a = 0; a < 8; a++) r[a] = ex[m * 72 + a2 * 9 + a];

    dft8(r);   // storage idx = lt*8 + s

    // ---- filter (coalesced: two float4 per thread) ----
    const float* f = g_filt + ((size_t)c * NJ + jr) * N + lt * 8;
    float4 fa = *(const float4*)(f);
    float4 fb = *(const float4*)(f + 4);
    r[0].x *= fa.x; r[0].y *= fa.x;  r[1].x *= fa.y; r[1].y *= fa.y;
    r[2].x *= fa.z; r[2].y *= fa.z;  r[3].x *= fa.w; r[3].y *= fa.w;
    r[4].x *= fb.x; r[4].y *= fb.x;  r[5].x *= fb.y; r[5].y *= fb.y;
    r[6].x *= fb.z; r[6].y *= fb.z;  r[7].x *= fb.w; r[7].y *= fb.w;

    // ---- inverse ----
    idft8(r);
    {
        float2 w[7];
        twpow7(cj(__ldg(&g_tw[a2 << 3])), w);   // mp == a2
#pragma unroll
        for (int i = 0; i < 7; i++) r[i + 1] = cmul(w[i], r[i + 1]);
    }
    GBAR(bar);   // WAR: fwd stage-2 reads done in all group threads
#pragma unroll
    for (int a = 0; a < 8; a++) ex[m * 72 + a2 * 9 + a] = r[a];
    GBAR(bar);
#pragma unroll
    for (int mq = 0; mq < 8; mq++) r[mq] = ex[m * 72 + mq * 9 + a2];
    GBAR(bar);

    idft8(r);
    inv_twB(r, a2, m);
#pragma unroll
    for (int b2 = 0; b2 < 8; b2++) ex[m * 72 + a2 + 8 * b2] = r[b2];
    GBAR(bar);
#pragma unroll
    for (int mq = 0; mq < 8; mq++) r[mq] = ex[mq * 72 + lt];

    idft8(r);   // natural h

#pragma unroll
    for (int b = 0; b < 8; b++) col[lt + 64 * b] = f2h(r[b]);
}

// ---------------------------------------------------------------------------
// K3: row inverse, C2R via packing.
// ---------------------------------------------------------------------------
__global__ void __launch_bounds__(256) k_rowifft(float* __restrict__ out) {
    __shared__ __half2 tile[NJ * 9 + 3];
    __shared__ float2 ex[4 * 576];
    int t = threadIdx.x;
    int img = blockIdx.y, h0 = blockIdx.x * 8;

    // coalesced transposed read of the half-spectrum for this block's 8 rows
    {
        int hh = t & 7, jc = t >> 3;
        const __half2* src = g_spec + (size_t)img * NJ * N + h0 + hh;
#pragma unroll
        for (int it = 0; it < 9; it++) {
            int j = jc + 32 * it;
            if (j < NJ) tile[j * 9 + hh] = src[(size_t)j * N];
        }
    }
    __syncthreads();

    int g = t >> 6, lt = t & 63;
    int bar = g + 1;
    int m = lt >> 3, a2 = lt & 7;
    int base = m + 8 * a2;

    // build Z in storage order: r[s] = Z[base + 64*s]
    float2 r[8];
#pragma unroll
    for (int s = 0; s < 8; s++) {
        int j = base + 64 * s;
        if (j <= 256) {
            float2 f1 = h2f(tile[j * 9 + 2 * g]);
            float2 f2 = h2f(tile[j * 9 + 2 * g + 1]);
            r[s] = make_float2(f1.x - f2.y, f1.y + f2.x);        // g1h1 + i*g1h2
        } else {
            int jm = N - j;
            float2 f1 = h2f(tile[jm * 9 + 2 * g]);
            float2 f2 = h2f(tile[jm * 9 + 2 * g + 1]);
            r[s] = make_float2(f1.x + f2.y, f2.x - f1.y);        // conj(g1h1)+i*conj(g1h2)
        }
    }

    float2* exg = ex + g * 576;

    idft8(r);
    {
        float2 w[7];
        twpow7(cj(__ldg(&g_tw[a2 << 3])), w);   // mp == a2
#pragma unroll
        for (int i = 0; i < 7; i++) r[i + 1] = cmul(w[i], r[i + 1]);
    }
#pragma unroll
    for (int a = 0; a < 8; a++) exg[m * 72 + a2 * 9 + a] = r[a];
    GBAR(bar);
#pragma unroll
    for (int mq = 0; mq < 8; mq++) r[mq] = exg[m * 72 + mq * 9 + a2];
    GBAR(bar);

    idft8(r);
    inv_twB(r, a2, m);
#pragma unroll
    for (int b2 = 0; b2 < 8; b2++) exg[m * 72 + a2 + 8 * b2] = r[b2];
    GBAR(bar);
#pragma unroll
    for (int mq = 0; mq < 8; mq++) r[mq] = exg[mq * 72 + lt];

    idft8(r);   // natural w; r = out[h1,w] + i*out[h2,w]

    float* o1 = out + ((size_t)img * N + h0 + 2 * g) * N;
    float* o2 = o1 + N;
#pragma unroll
    for (int b = 0; b < 8; b++) {
        o1[lt + 64 * b] = r[b].x;
        o2[lt + 64 * b] = r[b].y;
    }
}

// ---------------------------------------------------------------------------
extern "C" void kernel_launch(void* const* d_in, const int* in_sizes, int n_in,
                              void* d_out, int out_size) {
    int ix = 0, ip = 1;
    if (n_in >= 2 && in_sizes[0] == 3 * N * N) { ix = 1; ip = 0; }
    const float* x     = (const float*)d_in[ix];
    const float* param = (const float*)d_in[ip];
    float* out = (float*)d_out;

    k_tw<<<1, 512>>>();
    k_filter<<<(3 * NJ * N + 255) / 256, 256>>>(param);
    k_rowfft<<<dim3(N / 8, NIMG), 256>>>(x);
    k_colfft<<<dim3((NJ + 3) / 4, NIMG), 256>>>();
    k_rowifft<<<dim3(N / 8, NIMG), 256>>>(out);
}